// round 2
// baseline (speedup 1.0000x reference)
#include <cuda_runtime.h>
#include <cstdint>

#define NQ   14
#define TPB  512

// Storage swizzle: conflict-free for every access pattern used below.
__device__ __forceinline__ int phys_(int j) { return j ^ ((j >> 4) & 15); }

// Forward CNOT-chain index map: bit k of result = parity of bits k..13 of x.
__device__ __forceinline__ int pf_(int x) {
    x ^= x >> 1; x ^= x >> 2; x ^= x >> 4; x ^= x >> 8;
    return x;
}

// ---- packed f32x2 helpers (Blackwell FFMA2) ----
__device__ __forceinline__ float2 f2mul(float2 a, float2 b) {
    float2 r;
    asm("{\n\t.reg .b64 x,y,z;\n\t"
        "mov.b64 x,{%2,%3};\n\t"
        "mov.b64 y,{%4,%5};\n\t"
        "mul.rn.f32x2 z,x,y;\n\t"
        "mov.b64 {%0,%1},z;\n\t}"
        : "=f"(r.x), "=f"(r.y)
        : "f"(a.x), "f"(a.y), "f"(b.x), "f"(b.y));
    return r;
}
__device__ __forceinline__ float2 f2fma(float2 a, float2 b, float2 c) {
    float2 r;
    asm("{\n\t.reg .b64 x,y,z,w;\n\t"
        "mov.b64 x,{%2,%3};\n\t"
        "mov.b64 y,{%4,%5};\n\t"
        "mov.b64 z,{%6,%7};\n\t"
        "fma.rn.f32x2 w,x,y,z;\n\t"
        "mov.b64 {%0,%1},w;\n\t}"
        : "=f"(r.x), "=f"(r.y)
        : "f"(a.x), "f"(a.y), "f"(b.x), "f"(b.y), "f"(c.x), "f"(c.y));
    return r;
}

// RY rotation on a pair: u0' = ca*u0 - sa*u1 ; u1' = sa*u0 + ca*u1 (packed re/im).
__device__ __forceinline__ void ry_pair(float2& u0, float2& u1,
                                        float2 ca2, float2 sa2, float2 nsa2) {
    float2 t0 = f2fma(nsa2, u1, f2mul(ca2, u0));
    float2 t1 = f2fma(ca2,  u1, f2mul(sa2, u0));
    u0 = t0; u1 = t1;
}

// a * p, with p pre-split: px=(pr,pr), pm=(-pi,pi). Swap is register renaming.
__device__ __forceinline__ float2 cmulp(float2 a, float2 px, float2 pm) {
    float2 s = make_float2(a.y, a.x);
    return f2fma(px, a, f2mul(pm, s));
}

// scalar complex mul (LUT build only)
__device__ __forceinline__ float2 cmul_s(float2 a, float2 b) {
    return make_float2(a.x * b.x - a.y * b.y, a.x * b.y + a.y * b.x);
}

__global__ void __launch_bounds__(TPB, 1)
qsim_kernel(const float* __restrict__ sb,   // [B,14]
            const float* __restrict__ vp,   // [3,14,3]
            const float* __restrict__ hw,   // [1,14]
            const float* __restrict__ hb,   // [1]
            float* __restrict__ out)        // [B]
{
    extern __shared__ unsigned char smraw[];
    float2* psi = (float2*)smraw;                       // 131072 B
    float*  cx  = (float*)(smraw + 131072);             // 16
    float*  sx  = cx + 16;                              // 16
    float2* gRY = (float2*)(sx + 16);                   // 48 (42 used): (ca,sa)
    float2* phw = gRY + 48;                             // 48 (42 used): e^{i theta}
    float2* Plo = phw + 48;                             // 3*128
    float2* Phi = Plo + 384;                            // 3*128
    float*  Wlo = (float*)(Phi + 384);                  // 128
    float*  Whi = Wlo + 128;                            // 128
    float*  red = Whi + 128;                            // 16

    const int t = threadIdx.x;
    const int b = blockIdx.x;

    // ---- stage 1: tiny parameter staging ----
    if (t < NQ) {
        float s, c;
        sincosf(0.5f * sb[b * NQ + t], &s, &c);
        cx[t] = c; sx[t] = s;
    }
    if (t >= 64 && t < 64 + 3 * NQ) {
        int lw = t - 64;                         // L*14 + w
        float sa, ca, sp, cp;
        sincosf(0.5f * vp[lw * 3 + 0], &sa, &ca);
        sincosf(vp[lw * 3 + 1], &sp, &cp);       // RZ -> diag(1, e^{i theta})
        gRY[lw] = make_float2(ca, sa);
        phw[lw] = make_float2(cp, sp);
    }
    if (t >= 128 && t < 256) {                   // W for bits 0..6 (wires 13..7)
        int v = t - 128; float acc = 0.f;
        #pragma unroll
        for (int k = 0; k < 7; k++)
            acc += hw[13 - k] * (1.f - 2.f * (float)((v >> k) & 1));
        Wlo[v] = acc;
    }
    if (t >= 256 && t < 384) {                   // W for bits 7..13 (wires 6..0)
        int v = t - 256; float acc = 0.f;
        #pragma unroll
        for (int k = 0; k < 7; k++)
            acc += hw[6 - k] * (1.f - 2.f * (float)((v >> k) & 1));
        Whi[v] = acc;
    }
    __syncthreads();

    // ---- stage 2: per-layer consolidated RZ phase LUTs ----
    // Plo[L][v] = prod_{k<7, bit k of v} e^{i th(L, 13-k)}  (index bits 0..6)
    // Phi[L][v] = prod_{k<7, bit k of v} e^{i th(L, 6-k)}   (index bits 7..13)
    if (t < 384) {
        int L = t >> 7, vv = t & 127;
        float2 pl = make_float2(1.f, 0.f), ph = make_float2(1.f, 0.f);
        #pragma unroll
        for (int k = 0; k < 7; k++) {
            if ((vv >> k) & 1) {
                pl = cmul_s(pl, phw[L * NQ + (13 - k)]);
                ph = cmul_s(ph, phw[L * NQ + (6 - k)]);
            }
        }
        Plo[t] = pl; Phi[t] = ph;
    }

    float2 v[32];

    // ---- group-gate appliers (RY only; indices compile-time after unroll) ----
    auto applyA = [&](int L) {                   // wires 0..4 on bits 13..9
        #pragma unroll
        for (int lb = 0; lb < 5; lb++) {
            float2 g = gRY[L * NQ + (4 - lb)];
            float2 ca2 = make_float2(g.x, g.x);
            float2 sa2 = make_float2(g.y, g.y);
            float2 nsa2 = make_float2(-g.y, -g.y);
            #pragma unroll
            for (int m = 0; m < 16; m++) {
                int l0 = ((m >> lb) << (lb + 1)) | (m & ((1 << lb) - 1));
                ry_pair(v[l0], v[l0 | (1 << lb)], ca2, sa2, nsa2);
            }
        }
    };
    auto applyB = [&](int L) {                   // wires 5..9 on bits 8..4
        #pragma unroll
        for (int lb = 0; lb < 5; lb++) {
            float2 g = gRY[L * NQ + (9 - lb)];
            float2 ca2 = make_float2(g.x, g.x);
            float2 sa2 = make_float2(g.y, g.y);
            float2 nsa2 = make_float2(-g.y, -g.y);
            #pragma unroll
            for (int m = 0; m < 16; m++) {
                int l0 = ((m >> lb) << (lb + 1)) | (m & ((1 << lb) - 1));
                ry_pair(v[l0], v[l0 | (1 << lb)], ca2, sa2, nsa2);
            }
        }
    };
    auto applyC16 = [&](int L) {                 // wires 10..13 on bits 3..0
        #pragma unroll
        for (int lb = 0; lb < 4; lb++) {
            float2 g = gRY[L * NQ + (13 - lb)];
            float2 ca2 = make_float2(g.x, g.x);
            float2 sa2 = make_float2(g.y, g.y);
            float2 nsa2 = make_float2(-g.y, -g.y);
            #pragma unroll
            for (int m = 0; m < 8; m++) {
                int l0 = ((m >> lb) << (lb + 1)) | (m & ((1 << lb) - 1));
                ry_pair(v[l0], v[l0 | (1 << lb)], ca2, sa2, nsa2);
            }
        }
    };

    // ---- pass 0: closed-form RX product state + layer0 wires 0..4 ----
    {
        float mt = 1.f;
        #pragma unroll
        for (int k = 0; k < 9; k++)
            mt *= ((t >> k) & 1) ? sx[13 - k] : cx[13 - k];
        int pt = __popc(t);
        #pragma unroll
        for (int l = 0; l < 32; l++) {
            float m = mt;
            #pragma unroll
            for (int lb = 0; lb < 5; lb++)
                m *= ((l >> lb) & 1) ? sx[4 - lb] : cx[4 - lb];
            int k = (pt + __popc(l)) & 3;        // (-i)^k
            float2 a;
            a.x = (k == 0) ? m : ((k == 2) ? -m : 0.f);
            a.y = (k == 1) ? -m : ((k == 3) ? m : 0.f);
            v[l] = a;
        }
        applyA(0);
        #pragma unroll
        for (int l = 0; l < 32; l++)
            psi[phys_((l << 9) | t)] = v[l];
    }
    __syncthreads();

    #pragma unroll 1
    for (int L = 0; L < 3; L++) {
        // ---- pass B: wires 5..9 ----
        {
            const int hi = (t >> 4) << 9;
            const int lo = t & 15;
            #pragma unroll
            for (int l = 0; l < 32; l++)
                v[l] = psi[phys_(hi | (l << 4) | lo)];
            applyB(L);
            #pragma unroll
            for (int l = 0; l < 32; l++)
                psi[phys_(hi | (l << 4) | lo)] = v[l];
        }
        __syncthreads();

        // ---- pass C: wires 10..13 + consolidated layer phase ----
        #pragma unroll
        for (int h = 0; h < 2; h++) {
            const int tt = t + h * TPB;
            #pragma unroll
            for (int l = 0; l < 16; l++)
                v[l] = psi[phys_((tt << 4) | l)];
            applyC16(L);
            {
                float2 ph = Phi[L * 128 + (tt >> 3)];
                float2 phx = make_float2(ph.x, ph.x);
                float2 phm = make_float2(-ph.y, ph.y);
                const int lobase = (tt & 7) << 4;
                #pragma unroll
                for (int l = 0; l < 16; l++) {
                    float2 p = Plo[L * 128 + (lobase | l)];
                    float2 a = cmulp(v[l], make_float2(p.x, p.x),
                                           make_float2(-p.y, p.y));
                    v[l] = cmulp(a, phx, phm);
                }
            }
            #pragma unroll
            for (int l = 0; l < 16; l++)
                psi[phys_((tt << 4) | l)] = v[l];
        }
        __syncthreads();

        if (L < 2) {
            // ---- pass A' of next layer: CNOT-chain fold (read at F^{-1}(j)) ----
            #pragma unroll
            for (int l = 0; l < 32; l++) {
                int j = (l << 9) | t;
                v[l] = psi[phys_(j ^ (j >> 1))];
            }
            applyA(L + 1);
            __syncthreads();
            #pragma unroll
            for (int l = 0; l < 32; l++)
                psi[phys_((l << 9) | t)] = v[l];
            __syncthreads();
        }
    }

    // ---- measurement: final chain folded into weight lookup ----
    float acc = 0.f;
    #pragma unroll
    for (int k = 0; k < 32; k++) {
        int i = t + (k << 9);
        float2 a = psi[phys_(i)];
        int f = pf_(i);
        acc += (a.x * a.x + a.y * a.y) * (Wlo[f & 127] + Whi[f >> 7]);
    }
    #pragma unroll
    for (int o = 16; o > 0; o >>= 1)
        acc += __shfl_xor_sync(0xffffffffu, acc, o);
    if ((t & 31) == 0) red[t >> 5] = acc;
    __syncthreads();
    if (t == 0) {
        float s = 0.f;
        #pragma unroll
        for (int w = 0; w < TPB / 32; w++) s += red[w];
        out[b] = s + hb[0];
    }
}

extern "C" void kernel_launch(void* const* d_in, const int* in_sizes, int n_in,
                              void* d_out, int out_size) {
    const float* sb = (const float*)d_in[0];
    const float* vp = (const float*)d_in[1];
    const float* hw = (const float*)d_in[2];
    const float* hb = (const float*)d_in[3];
    float* out = (float*)d_out;

    const int B = in_sizes[0] / NQ;
    const size_t smem = 131072                 // psi
                      + 64 + 64                // cx, sx
                      + 48 * 8 + 48 * 8        // gRY, phw
                      + 384 * 8 + 384 * 8      // Plo, Phi
                      + 512 + 512              // Wlo, Whi
                      + 64;                    // red
    cudaFuncSetAttribute(qsim_kernel,
                         cudaFuncAttributeMaxDynamicSharedMemorySize, (int)smem);
    qsim_kernel<<<B, TPB, smem>>>(sb, vp, hw, hb, out);
}